// round 11
// baseline (speedup 1.0000x reference)
#include <cuda_runtime.h>
#include <cuda_fp16.h>
#include <cuda_bf16.h>
#include <cstdint>

#define NMAX 50000
#define EMAX 800000
#define D 128
#define H 8
#define ATT_SCALE 0.25f   // 1/sqrt(16)
#define NEG_INF __int_as_float(0xff800000)

// ---------------- scratch (device globals; no runtime allocation) ----------
__device__ __align__(16) float  g_q[NMAX * D];
__device__ __align__(16) __half g_kh[NMAX * D];
__device__ __align__(16) __half g_vh[NMAX * D];
__device__ __align__(16) float  g_s[NMAX * D];
// packed bf16 hi/lo X operand (k-pair-packed words), written by x_prep (L0)
// and by the attention epilogue (L1 input)
__device__ __align__(16) uint32_t g_xh[NMAX * 64];
__device__ __align__(16) uint32_t g_xl[NMAX * 64];
// packed bf16 hi/lo weights: [layer*4+which][kpair*128+n]
__device__ __align__(16) uint32_t g_wph[8][8192];
__device__ __align__(16) uint32_t g_wpl[8][8192];
__device__ int   g_src[EMAX];
__device__ int   g_dst[EMAX];
__device__ int   g_rowptr[NMAX + 1];
__device__ int   g_cursor[NMAX + 1];
__device__ int   g_csrc[EMAX];                    // CSR: src node per incoming edge
__device__ int   g_blocksums[64];
__device__ int   g_is64;

// ---------------- bf16 split helpers ----------------------------------------
__device__ __forceinline__ void split_bf16(float x, __nv_bfloat16& hi, __nv_bfloat16& lo)
{
    hi = __float2bfloat16_rn(x);
    lo = __float2bfloat16_rn(x - __bfloat162float(hi));
}

__device__ __forceinline__ uint32_t pack_bf16(__nv_bfloat16 a, __nv_bfloat16 b)
{
    __nv_bfloat162 p = __nv_bfloat162(a, b);   // a in low 16 bits
    return *reinterpret_cast<uint32_t*>(&p);
}

__device__ __forceinline__ void mma_bf16(float* c, const uint32_t* a,
                                         uint32_t b0, uint32_t b1)
{
    asm volatile(
        "mma.sync.aligned.m16n8k16.row.col.f32.bf16.bf16.f32 "
        "{%0,%1,%2,%3}, {%4,%5,%6,%7}, {%8,%9}, {%0,%1,%2,%3};"
        : "+f"(c[0]), "+f"(c[1]), "+f"(c[2]), "+f"(c[3])
        : "r"(a[0]), "r"(a[1]), "r"(a[2]), "r"(a[3]), "r"(b0), "r"(b1));
}

// ---------------- edge_index dtype detection ------------------------------
__global__ void detect_kernel(const int* __restrict__ ei32)
{
    __shared__ int any_nonzero;
    if (threadIdx.x == 0) any_nonzero = 0;
    __syncthreads();
    int v = ei32[2 * threadIdx.x + 1];
    if (v != 0) any_nonzero = 1;
    __syncthreads();
    if (threadIdx.x == 0) g_is64 = any_nonzero ? 0 : 1;
}

__global__ void zero_cnt_kernel(int N)
{
    int i = blockIdx.x * blockDim.x + threadIdx.x;
    if (i <= N) g_rowptr[i] = 0;
}

// fused convert + histogram
__global__ void convert_hist_kernel(const int* __restrict__ ei32, int E)
{
    int e = blockIdx.x * blockDim.x + threadIdx.x;
    if (e >= E) return;
    int s, d;
    if (g_is64) {
        s = ei32[2 * (size_t)e];
        d = ei32[2 * ((size_t)E + e)];
    } else {
        s = ei32[e];
        d = ei32[(size_t)E + e];
    }
    g_src[e] = s;
    g_dst[e] = d;
    atomicAdd(&g_rowptr[d], 1);
}

// block-level exclusive scan: 1024 elements per block (in place on g_rowptr)
__global__ void scan1_kernel(int Ntot)
{
    __shared__ int sh[1024];
    int t = threadIdx.x;
    int i = blockIdx.x * 1024 + t;
    int v = (i < Ntot) ? g_rowptr[i] : 0;
    sh[t] = v;
    for (int off = 1; off < 1024; off <<= 1) {
        __syncthreads();
        int x = (t >= off) ? sh[t - off] : 0;
        __syncthreads();
        sh[t] += x;
    }
    __syncthreads();
    if (i < Ntot) g_rowptr[i] = sh[t] - v;      // exclusive
    if (t == 1023) g_blocksums[blockIdx.x] = sh[t];
}

__global__ void scan2_kernel(int nb)
{
    if (threadIdx.x == 0) {
        int acc = 0;
        for (int b = 0; b < nb; b++) {
            int x = g_blocksums[b];
            g_blocksums[b] = acc;
            acc += x;
        }
    }
}

__global__ void scan3_kernel(int Ntot)
{
    int i = blockIdx.x * 1024 + threadIdx.x;
    if (i < Ntot) {
        int r = g_rowptr[i] + g_blocksums[blockIdx.x];
        g_rowptr[i] = r;
        g_cursor[i] = r;
    }
}

__global__ void scatter_kernel(int E)
{
    int e = blockIdx.x * blockDim.x + threadIdx.x;
    if (e >= E) return;
    int pos = atomicAdd(&g_cursor[g_dst[e]], 1);
    g_csrc[pos] = g_src[e];
}

// ---------------- weight pre-split: 8 matrices -> packed hi/lo --------------
// grid = 256 blocks x 256 threads; 32 blocks per matrix (8192 words each)
__global__ void w_prep_kernel(
    const float* __restrict__ w0, const float* __restrict__ w1,
    const float* __restrict__ w2, const float* __restrict__ w3,
    const float* __restrict__ w4, const float* __restrict__ w5,
    const float* __restrict__ w6, const float* __restrict__ w7)
{
    const float* ws[8] = {w0, w1, w2, w3, w4, w5, w6, w7};
    int widx = blockIdx.x >> 5;
    int word = ((blockIdx.x & 31) << 8) + threadIdx.x;   // 0..8191
    int kp = word >> 7;
    int n  = word & 127;
    const float* W = ws[widx];
    float a = W[(size_t)(2 * kp) * 128 + n];
    float b = W[(size_t)(2 * kp + 1) * 128 + n];
    __nv_bfloat16 ah, al, bh, bl;
    split_bf16(a, ah, al);
    split_bf16(b, bh, bl);
    g_wph[widx][word] = pack_bf16(ah, bh);
    g_wpl[widx][word] = pack_bf16(al, bl);
}

// ---------------- X pre-split (layer 0 input) -------------------------------
__global__ void x_prep_kernel(const float* __restrict__ x, int N)
{
    int t = blockIdx.x * blockDim.x + threadIdx.x;
    if (t >= N * 32) return;
    int m = t >> 5;
    int c = (t & 31) * 4;
    float4 xv = *(const float4*)(x + (size_t)m * 128 + c);
    __nv_bfloat16 h0, l0, h1, l1, h2, l2, h3, l3;
    split_bf16(xv.x, h0, l0); split_bf16(xv.y, h1, l1);
    split_bf16(xv.z, h2, l2); split_bf16(xv.w, h3, l3);
    int wi = m * 64 + (c >> 1);
    *(uint2*)&g_xh[wi] = make_uint2(pack_bf16(h0, h1), pack_bf16(h2, h3));
    *(uint2*)&g_xl[wi] = make_uint2(pack_bf16(l0, l1), pack_bf16(l2, l3));
}

// ---------------- fused GEMM: {q,k,v,s} = X @ W_i + b_i (bf16-split MMA) ----
// grid = (4, ceil(N/128)); block = 256 (8 warps, 4x2); warp tile 32x64
// operands pre-split+packed in global; hot loop = LDG/STS/LDS/MMA only.
#define XPW 12    // words per X row (8 pairs + pad) -> conflict-free frags
#define WPW 132   // words per W pair-row (128 + pad) -> conflict-free frags

__global__ __launch_bounds__(256, 2) void gemm4_kernel(
    int layer,
    const float* __restrict__ bq, const float* __restrict__ bk,
    const float* __restrict__ bv, const float* __restrict__ bs,
    int N)
{
    int which = blockIdx.x;
    int widx = layer * 4 + which;
    const float* bias = (which == 0) ? bq : (which == 1) ? bk : (which == 2) ? bv : bs;

    __shared__ uint32_t Xph[2][128 * XPW];
    __shared__ uint32_t Xpl[2][128 * XPW];
    __shared__ uint32_t Wph[2][8 * WPW];
    __shared__ uint32_t Wpl[2][8 * WPW];

    int tid  = threadIdx.x;
    int lane = tid & 31;
    int warp = tid >> 5;
    int wm   = warp & 3;          // m offset = wm*32
    int wn   = warp >> 2;         // n offset = wn*64
    int lx   = lane & 3;          // threadID_in_group (t)
    int ly   = lane >> 2;         // groupID (g)
    int row0 = blockIdx.y * 128;

    // X loader coords: 2 uint2 (hi) + 2 uint2 (lo) per thread per step
    int xm[2], xw[2];
#pragma unroll
    for (int l = 0; l < 2; l++) {
        int f = tid + l * 256;
        xm[l] = f >> 2;               // row in tile
        xw[l] = (f & 3) * 2;          // word offset within step's 8 words
    }
    // W loader: one uint4 (hi) + uint4 (lo) per thread per step
    int wkp = tid >> 5;               // pair-row 0..7
    int wn0 = (tid & 31) * 4;         // 4 consecutive n-words

    float acc[2][8][4];
#pragma unroll
    for (int i = 0; i < 2; i++)
#pragma unroll
        for (int j = 0; j < 8; j++)
#pragma unroll
            for (int t = 0; t < 4; t++) acc[i][j][t] = 0.f;

    uint2 xh[2], xl[2];
    uint4 wh, wl;
    const uint2 z2 = make_uint2(0u, 0u);

    // prologue: load step 0, store into buffer 0
#pragma unroll
    for (int l = 0; l < 2; l++) {
        int gr = row0 + xm[l];
        int gi = gr * 64 + xw[l];
        xh[l] = (gr < N) ? *(const uint2*)&g_xh[gi] : z2;
        xl[l] = (gr < N) ? *(const uint2*)&g_xl[gi] : z2;
    }
    wh = *(const uint4*)&g_wph[widx][wkp * 128 + wn0];
    wl = *(const uint4*)&g_wpl[widx][wkp * 128 + wn0];
#pragma unroll
    for (int l = 0; l < 2; l++) {
        *(uint2*)&Xph[0][xm[l] * XPW + xw[l]] = xh[l];
        *(uint2*)&Xpl[0][xm[l] * XPW + xw[l]] = xl[l];
    }
    *(uint4*)&Wph[0][wkp * WPW + wn0] = wh;
    *(uint4*)&Wpl[0][wkp * WPW + wn0] = wl;
    __syncthreads();

    for (int step = 0; step < 8; step++) {
        int cur = step & 1;
        int nxt = cur ^ 1;

        // issue next tile's global loads (latency hidden under MMA)
        if (step < 7) {
            int kkp = (step + 1) * 8;
#pragma unroll
            for (int l = 0; l < 2; l++) {
                int gr = row0 + xm[l];
                int gi = gr * 64 + kkp + xw[l];
                xh[l] = (gr < N) ? *(const uint2*)&g_xh[gi] : z2;
                xl[l] = (gr < N) ? *(const uint2*)&g_xl[gi] : z2;
            }
            wh = *(const uint4*)&g_wph[widx][(kkp + wkp) * 128 + wn0];
            wl = *(const uint4*)&g_wpl[widx][(kkp + wkp) * 128 + wn0];
        }

        // one k16 MMA step from buf[cur]
        uint32_t ah[2][4], al[2][4];
#pragma unroll
        for (int i = 0; i < 2; i++) {
            int r = wm * 32 + i * 16 + ly;
            ah[i][0] = Xph[cur][r * XPW + lx];
            ah[i][1] = Xph[cur][(r + 8) * XPW + lx];
            ah[i][2] = Xph[cur][r * XPW + lx + 4];
            ah[i][3] = Xph[cur][(r + 8) * XPW + lx + 4];
            al[i][0] = Xpl[cur][r * XPW + lx];
            al[i][1] = Xpl[cur][(r + 8) * XPW + lx];
            al[i][2] = Xpl[cur][r * XPW + lx + 4];
            al[i][3] = Xpl[cur][(r + 8) * XPW + lx + 4];
        }
#pragma unroll
        for (int j = 0; j < 8; j++) {
            int n = wn * 64 + j * 8 + ly;
            uint32_t bh0 = Wph[cur][lx * WPW + n];
            uint32_t bh1 = Wph[cur][(lx + 4) * WPW + n];
            uint32_t bl0 = Wpl[cur][lx * WPW + n];
            uint32_t bl1 = Wpl[cur][(lx + 4) * WPW + n];
#pragma unroll
            for (int i = 0; i < 2; i++) {
                mma_bf16(acc[i][j], ah[i], bh0, bh1);   // Ah*Bh
                mma_bf16(acc[i][j], al[i], bh0, bh1);   // Al*Bh
                mma_bf16(acc[i][j], ah[i], bl0, bl1);   // Ah*Bl
            }
        }

        // store next tile into buf[nxt]
        if (step < 7) {
#pragma unroll
            for (int l = 0; l < 2; l++) {
                *(uint2*)&Xph[nxt][xm[l] * XPW + xw[l]] = xh[l];
                *(uint2*)&Xpl[nxt][xm[l] * XPW + xw[l]] = xl[l];
            }
            *(uint4*)&Wph[nxt][wkp * WPW + wn0] = wh;
            *(uint4*)&Wpl[nxt][wkp * WPW + wn0] = wl;
        }
        __syncthreads();
    }

    // epilogue: bias add + guarded store (c0,c1 at row; c2,c3 at row+8)
    bool is_half = (which == 1) || (which == 2);
    float*  Yf = (which == 0) ? g_q : g_s;
    __half* Yh = (which == 1) ? g_kh : g_vh;

#pragma unroll
    for (int i = 0; i < 2; i++) {
        int rg = row0 + wm * 32 + i * 16 + ly;
#pragma unroll
        for (int j = 0; j < 8; j++) {
            int cg = wn * 64 + j * 8 + 2 * lx;
            float2 bb = *(const float2*)(bias + cg);
            float o00 = acc[i][j][0] + bb.x, o01 = acc[i][j][1] + bb.y;
            float o10 = acc[i][j][2] + bb.x, o11 = acc[i][j][3] + bb.y;
            if (is_half) {
                if (rg < N)
                    *(__half2*)(Yh + (size_t)rg * 128 + cg) = __floats2half2_rn(o00, o01);
                if (rg + 8 < N)
                    *(__half2*)(Yh + (size_t)(rg + 8) * 128 + cg) = __floats2half2_rn(o10, o11);
            } else {
                if (rg < N)
                    *(float2*)(Yf + (size_t)rg * 128 + cg) = make_float2(o00, o01);
                if (rg + 8 < N)
                    *(float2*)(Yf + (size_t)(rg + 8) * 128 + cg) = make_float2(o10, o11);
            }
        }
    }
}

// ---------------- fused attention: gather + online softmax + skip ----------
// TWO nodes per warp: each 16-lane half handles one node, 8 channels per lane.
// Layer 0 (outp==null): epilogue writes packed bf16 hi/lo X for layer-1 GEMM.
__device__ __forceinline__ float dot8(float4 q0, float4 q1, uint4 u)
{
    float2 f0 = __half22float2(*reinterpret_cast<__half2*>(&u.x));
    float2 f1 = __half22float2(*reinterpret_cast<__half2*>(&u.y));
    float2 f2 = __half22float2(*reinterpret_cast<__half2*>(&u.z));
    float2 f3 = __half22float2(*reinterpret_cast<__half2*>(&u.w));
    return q0.x * f0.x + q0.y * f0.y + q0.z * f1.x + q0.w * f1.y
         + q1.x * f2.x + q1.y * f2.y + q1.z * f3.x + q1.w * f3.y;
}

__device__ __forceinline__ void acc8(float4& a0, float4& a1, float w, uint4 u)
{
    float2 f0 = __half22float2(*reinterpret_cast<__half2*>(&u.x));
    float2 f1 = __half22float2(*reinterpret_cast<__half2*>(&u.y));
    float2 f2 = __half22float2(*reinterpret_cast<__half2*>(&u.z));
    float2 f3 = __half22float2(*reinterpret_cast<__half2*>(&u.w));
    a0.x += w * f0.x; a0.y += w * f0.y; a0.z += w * f1.x; a0.w += w * f1.y;
    a1.x += w * f2.x; a1.y += w * f2.y; a1.z += w * f3.x; a1.w += w * f3.y;
}

__global__ void attn_gather_kernel(float* __restrict__ outp, int N, int do_relu)
{
    int warp_id = blockIdx.x * 8 + (threadIdx.x >> 5);
    int lane = threadIdx.x & 31;
    int half = lane >> 4;                 // 0 or 1: which node in this warp
    int hl   = lane & 15;                 // lane within half; channels [8hl, 8hl+8)
    int node = warp_id * 2 + half;
    if (node >= N) return;
    unsigned mask = 0xFFFFu << (half * 16);

    size_t off = (size_t)node * D;
    float4 q0 = *((const float4*)(g_q + off) + 2 * hl);
    float4 q1 = *((const float4*)(g_q + off) + 2 * hl + 1);

    int beg = g_rowptr[node];
    int end = g_rowptr[node + 1];

    float m = NEG_INF;
    float den = 0.f;
    float4 acc0 = make_float4(0.f, 0.f, 0.f, 0.f);
    float4 acc1 = make_float4(0.f, 0.f, 0.f, 0.f);

    int i = beg;
    for (; i + 4 <= end; i += 4) {
        int s0 = __ldg(&g_csrc[i]);
        int s1 = __ldg(&g_csrc[i + 1]);
        int s2 = __ldg(&g_csrc[i + 2]);
        int s3 = __ldg(&g_csrc[i + 3]);
        uint4 k0 = __ldg((const uint4*)(g_kh + (size_t)s0 * D) + hl);
        uint4 k1 = __ldg((const uint4*)(g_kh + (size_t)s1 * D) + hl);
        uint4 k2 = __ldg((const uint4*)(g_kh + (size_t)s2 * D) + hl);
        uint4 k3 = __ldg((const uint4*)(g_kh + (size_t)s3 * D) + hl);
        uint4 v0 = __ldg((const uint4*)(g_vh + (size_t)s0 * D) + hl);
        uint4 v1 = __ldg((const uint4*)(g_vh + (size_t)s1 * D) + hl);
        uint4 v2 = __ldg((const uint4*)(g_vh + (size_t)s2 * D) + hl);
        uint4 v3 = __ldg((const uint4*)(g_vh + (size_t)s3 * D) + hl);

        float a0 = dot8(q0, q1, k0);
        float a1 = dot8(q0, q1, k1);
        float a2 = dot8(q0, q1, k2);
        float a3 = dot8(q0, q1, k3);
        a0 = (a0 + __shfl_xor_sync(mask, a0, 1)) * ATT_SCALE;
        a1 = (a1 + __shfl_xor_sync(mask, a1, 1)) * ATT_SCALE;
        a2 = (a2 + __shfl_xor_sync(mask, a2, 1)) * ATT_SCALE;
        a3 = (a3 + __shfl_xor_sync(mask, a3, 1)) * ATT_SCALE;

        float mx = fmaxf(fmaxf(a0, a1), fmaxf(a2, a3));
        float newm = fmaxf(m, mx);
        float c  = __expf(m - newm);      // first group: exp(-inf)=0
        float w0 = __expf(a0 - newm);
        float w1 = __expf(a1 - newm);
        float w2 = __expf(a2 - newm);
        float w3 = __expf(a3 - newm);
        den = den * c + (w0 + w1) + (w2 + w3);
        acc0.x *= c; acc0.y *= c; acc0.z *= c; acc0.w *= c;
        acc1.x *= c; acc1.y *= c; acc1.z *= c; acc1.w *= c;
        acc8(acc0, acc1, w0, v0);
        acc8(acc0, acc1, w1, v1);
        acc8(acc0, acc1, w2, v2);
        acc8(acc0, acc1, w3, v3);
        m = newm;
    }
    for (; i < end; i++) {
        int s = __ldg(&g_csrc[i]);
        uint4 kv = __ldg((const uint4*)(g_kh + (size_t)s * D) + hl);
        uint4 vv = __ldg((const uint4*)(g_vh + (size_t)s * D) + hl);
        float a = dot8(q0, q1, kv);
        a = (a + __shfl_xor_sync(mask, a, 1)) * ATT_SCALE;
        float newm = fmaxf(m, a);
        float c = __expf(m - newm);
        float w = __expf(a - newm);
        den = den * c + w;
        acc0.x *= c; acc0.y *= c; acc0.z *= c; acc0.w *= c;
        acc1.x *= c; acc1.y *= c; acc1.z *= c; acc1.w *= c;
        acc8(acc0, acc1, w, vv);
        m = newm;
    }

    float4 sv0 = *((const float4*)(g_s + off) + 2 * hl);
    float4 sv1 = *((const float4*)(g_s + off) + 2 * hl + 1);
    float inv = (den > 0.f) ? 1.f / den : 0.f;
    float o[8];
    o[0] = sv0.x + acc0.x * inv; o[1] = sv0.y + acc0.y * inv;
    o[2] = sv0.z + acc0.z * inv; o[3] = sv0.w + acc0.w * inv;
    o[4] = sv1.x + acc1.x * inv; o[5] = sv1.y + acc1.y * inv;
    o[6] = sv1.z + acc1.z * inv; o[7] = sv1.w + acc1.w * inv;
    if (do_relu) {
#pragma unroll
        for (int t = 0; t < 8; t++) o[t] = fmaxf(o[t], 0.f);
    }

    if (outp) {
        *((float4*)(outp + off) + 2 * hl)     = make_float4(o[0], o[1], o[2], o[3]);
        *((float4*)(outp + off) + 2 * hl + 1) = make_float4(o[4], o[5], o[6], o[7]);
    } else {
        // pack for layer-1 GEMM: 4 hi words + 4 lo words per lane
        __nv_bfloat16 hb[8], lb[8];
#pragma unroll
        for (int t = 0; t < 8; t++) split_bf16(o[t], hb[t], lb[t]);
        int wi = node * 64 + 4 * hl;
        *(uint4*)&g_xh[wi] = make_uint4(pack_bf16(hb[0], hb[1]), pack_bf16(hb[2], hb[3]),
                                        pack_bf16(hb[4], hb[5]), pack_bf16(hb[6], hb[7]));
        *(uint4*)&g_xl[wi] = make_uint4(pack_bf16(lb[0], lb[1]), pack_bf16(lb[2], lb[3]),
                                        pack_bf16(lb[4], lb[5]), pack_bf16(lb[6], lb[7]));
    }
}

// ---------------- host ------------------------------------------------------
extern "C" void kernel_launch(void* const* d_in, const int* in_sizes, int n_in,
                              void* d_out, int out_size)
{
    const float* x = (const float*)d_in[0];
    const int* ei32 = (const int*)d_in[1];
    int N = in_sizes[0] / 128;
    int E = in_sizes[1] / 2;

    const float* W[2][4] = {
        {(const float*)d_in[3], (const float*)d_in[5], (const float*)d_in[7], (const float*)d_in[9]},
        {(const float*)d_in[11], (const float*)d_in[13], (const float*)d_in[15], (const float*)d_in[17]}
    };
    const float* B[2][4] = {
        {(const float*)d_in[4], (const float*)d_in[6], (const float*)d_in[8], (const float*)d_in[10]},
        {(const float*)d_in[12], (const float*)d_in[14], (const float*)d_in[16], (const float*)d_in[18]}
    };

    // one-time side stream + fork/join events (resources only; work is
    // identical on every call)
    static cudaStream_t s2 = nullptr;
    static cudaEvent_t evFork = nullptr, evW = nullptr, evJoin = nullptr;
    if (!s2) {
        cudaStreamCreateWithFlags(&s2, cudaStreamNonBlocking);
        cudaEventCreateWithFlags(&evFork, cudaEventDisableTiming);
        cudaEventCreateWithFlags(&evW, cudaEventDisableTiming);
        cudaEventCreateWithFlags(&evJoin, cudaEventDisableTiming);
    }

    int Ntot = N + 1;
    int nscan = (Ntot + 1023) / 1024;

    // fork: weight prep + CSR build on s2
    cudaEventRecord(evFork, 0);
    cudaStreamWaitEvent(s2, evFork, 0);
    w_prep_kernel<<<256, 256, 0, s2>>>(W[0][0], W[0][1], W[0][2], W[0][3],
                                       W[1][0], W[1][1], W[1][2], W[1][3]);
    cudaEventRecord(evW, s2);
    detect_kernel<<<1, 256, 0, s2>>>(ei32);
    zero_cnt_kernel<<<(Ntot + 255) / 256, 256, 0, s2>>>(N);
    convert_hist_kernel<<<(E + 255) / 256, 256, 0, s2>>>(ei32, E);
    scan1_kernel<<<nscan, 1024, 0, s2>>>(Ntot);
    scan2_kernel<<<1, 32, 0, s2>>>(nscan);
    scan3_kernel<<<nscan, 1024, 0, s2>>>(Ntot);
    scatter_kernel<<<(E + 255) / 256, 256, 0, s2>>>(E);
    cudaEventRecord(evJoin, s2);

    dim3 ggrid(4, (N + 127) / 128);
    int attn_blocks = (N + 15) / 16;   // 2 nodes per warp, 8 warps per block

    // main: X prep for layer 0 (runs parallel with w_prep on s2)
    x_prep_kernel<<<(N * 32 + 255) / 256, 256>>>(x, N);
    cudaStreamWaitEvent(0, evW, 0);      // weights packed

    // layer 0
    gemm4_kernel<<<ggrid, 256>>>(0, B[0][0], B[0][1], B[0][2], B[0][3], N);
    cudaStreamWaitEvent(0, evJoin, 0);   // join: attention needs CSR
    attn_gather_kernel<<<attn_blocks, 256>>>(nullptr, N, 1);  // writes packed X

    // layer 1
    gemm4_kernel<<<ggrid, 256>>>(1, B[1][0], B[1][1], B[1][2], B[1][3], N);
    attn_gather_kernel<<<attn_blocks, 256>>>((float*)d_out, N, 0);
}

// round 12
// speedup vs baseline: 1.0488x; 1.0488x over previous
#include <cuda_runtime.h>
#include <cuda_fp16.h>
#include <cuda_bf16.h>
#include <cstdint>

#define NMAX 50000
#define EMAX 800000
#define D 128
#define H 8
#define ATT_SCALE 0.25f   // 1/sqrt(16)
#define NEG_INF __int_as_float(0xff800000)

// ---------------- scratch (device globals; no runtime allocation) ----------
__device__ __align__(16) float  g_q[NMAX * D];
__device__ __align__(16) __half g_kh[NMAX * D];
__device__ __align__(16) __half g_vh[NMAX * D];
__device__ __align__(16) float  g_s[NMAX * D];
// packed bf16 hi/lo X operand for layer-1 GEMM (written by attention epilogue)
__device__ __align__(16) uint32_t g_xh[NMAX * 64];
__device__ __align__(16) uint32_t g_xl[NMAX * 64];
// packed bf16 hi/lo weights: [layer*4+which][kpair*128+n]
__device__ __align__(16) uint32_t g_wph[8][8192];
__device__ __align__(16) uint32_t g_wpl[8][8192];
__device__ int   g_src[EMAX];
__device__ int   g_dst[EMAX];
__device__ int   g_rowptr[NMAX + 1];
__device__ int   g_cursor[NMAX + 1];
__device__ int   g_csrc[EMAX];                    // CSR: src node per incoming edge
__device__ int   g_blocksums[64];
__device__ int   g_is64;

// ---------------- bf16 split helpers ----------------------------------------
__device__ __forceinline__ void split_bf16(float x, __nv_bfloat16& hi, __nv_bfloat16& lo)
{
    hi = __float2bfloat16_rn(x);
    lo = __float2bfloat16_rn(x - __bfloat162float(hi));
}

__device__ __forceinline__ uint32_t pack_bf16(__nv_bfloat16 a, __nv_bfloat16 b)
{
    __nv_bfloat162 p = __nv_bfloat162(a, b);   // a in low 16 bits
    return *reinterpret_cast<uint32_t*>(&p);
}

__device__ __forceinline__ void mma_bf16(float* c, const uint32_t* a,
                                         uint32_t b0, uint32_t b1)
{
    asm volatile(
        "mma.sync.aligned.m16n8k16.row.col.f32.bf16.bf16.f32 "
        "{%0,%1,%2,%3}, {%4,%5,%6,%7}, {%8,%9}, {%0,%1,%2,%3};"
        : "+f"(c[0]), "+f"(c[1]), "+f"(c[2]), "+f"(c[3])
        : "r"(a[0]), "r"(a[1]), "r"(a[2]), "r"(a[3]), "r"(b0), "r"(b1));
}

// ---------------- edge_index dtype detection ------------------------------
__global__ void detect_kernel(const int* __restrict__ ei32)
{
    __shared__ int any_nonzero;
    if (threadIdx.x == 0) any_nonzero = 0;
    __syncthreads();
    int v = ei32[2 * threadIdx.x + 1];
    if (v != 0) any_nonzero = 1;
    __syncthreads();
    if (threadIdx.x == 0) g_is64 = any_nonzero ? 0 : 1;
}

__global__ void zero_cnt_kernel(int N)
{
    int i = blockIdx.x * blockDim.x + threadIdx.x;
    if (i <= N) g_rowptr[i] = 0;
}

// fused convert + histogram
__global__ void convert_hist_kernel(const int* __restrict__ ei32, int E)
{
    int e = blockIdx.x * blockDim.x + threadIdx.x;
    if (e >= E) return;
    int s, d;
    if (g_is64) {
        s = ei32[2 * (size_t)e];
        d = ei32[2 * ((size_t)E + e)];
    } else {
        s = ei32[e];
        d = ei32[(size_t)E + e];
    }
    g_src[e] = s;
    g_dst[e] = d;
    atomicAdd(&g_rowptr[d], 1);
}

// block-level exclusive scan: 1024 elements per block (in place on g_rowptr)
__global__ void scan1_kernel(int Ntot)
{
    __shared__ int sh[1024];
    int t = threadIdx.x;
    int i = blockIdx.x * 1024 + t;
    int v = (i < Ntot) ? g_rowptr[i] : 0;
    sh[t] = v;
    for (int off = 1; off < 1024; off <<= 1) {
        __syncthreads();
        int x = (t >= off) ? sh[t - off] : 0;
        __syncthreads();
        sh[t] += x;
    }
    __syncthreads();
    if (i < Ntot) g_rowptr[i] = sh[t] - v;      // exclusive
    if (t == 1023) g_blocksums[blockIdx.x] = sh[t];
}

__global__ void scan2_kernel(int nb)
{
    if (threadIdx.x == 0) {
        int acc = 0;
        for (int b = 0; b < nb; b++) {
            int x = g_blocksums[b];
            g_blocksums[b] = acc;
            acc += x;
        }
    }
}

__global__ void scan3_kernel(int Ntot)
{
    int i = blockIdx.x * 1024 + threadIdx.x;
    if (i < Ntot) {
        int r = g_rowptr[i] + g_blocksums[blockIdx.x];
        g_rowptr[i] = r;
        g_cursor[i] = r;
    }
}

__global__ void scatter_kernel(int E)
{
    int e = blockIdx.x * blockDim.x + threadIdx.x;
    if (e >= E) return;
    int pos = atomicAdd(&g_cursor[g_dst[e]], 1);
    g_csrc[pos] = g_src[e];
}

// ---------------- weight pre-split: 8 matrices -> packed hi/lo --------------
// grid = 256 blocks x 256 threads; 32 blocks per matrix (8192 words each)
__global__ void w_prep_kernel(
    const float* __restrict__ w0, const float* __restrict__ w1,
    const float* __restrict__ w2, const float* __restrict__ w3,
    const float* __restrict__ w4, const float* __restrict__ w5,
    const float* __restrict__ w6, const float* __restrict__ w7)
{
    const float* ws[8] = {w0, w1, w2, w3, w4, w5, w6, w7};
    int widx = blockIdx.x >> 5;
    int word = ((blockIdx.x & 31) << 8) + threadIdx.x;   // 0..8191
    int kp = word >> 7;
    int n  = word & 127;
    const float* W = ws[widx];
    float a = W[(size_t)(2 * kp) * 128 + n];
    float b = W[(size_t)(2 * kp + 1) * 128 + n];
    __nv_bfloat16 ah, al, bh, bl;
    split_bf16(a, ah, al);
    split_bf16(b, bh, bl);
    g_wph[widx][word] = pack_bf16(ah, bh);
    g_wpl[widx][word] = pack_bf16(al, bl);
}

// ---------------- fused GEMM: {q,k,v,s} = X @ W_i + b_i (bf16-split MMA) ----
// grid = (4, ceil(N/128)); block = 256 (8 warps, 4x2); warp tile 32x64
// W always pre-packed. PACKED=false: X read fp32 + split in-kernel (layer 0).
// PACKED=true: X read from packed g_xh/g_xl (layer 1, written by attention).
#define XPW 12    // words per X row (8 pairs + pad) -> conflict-free frags
#define WPW 132   // words per W pair-row (128 + pad) -> conflict-free frags

template<bool PACKED>
__global__ __launch_bounds__(256, 2) void gemm4_kernel(
    const float* __restrict__ Xf, int layer,
    const float* __restrict__ bq, const float* __restrict__ bk,
    const float* __restrict__ bv, const float* __restrict__ bs,
    int N)
{
    int which = blockIdx.x;
    int widx = layer * 4 + which;
    const float* bias = (which == 0) ? bq : (which == 1) ? bk : (which == 2) ? bv : bs;

    __shared__ uint32_t Xph[2][128 * XPW];
    __shared__ uint32_t Xpl[2][128 * XPW];
    __shared__ uint32_t Wph[2][8 * WPW];
    __shared__ uint32_t Wpl[2][8 * WPW];

    int tid  = threadIdx.x;
    int lane = tid & 31;
    int warp = tid >> 5;
    int wm   = warp & 3;          // m offset = wm*32
    int wn   = warp >> 2;         // n offset = wn*64
    int lx   = lane & 3;          // threadID_in_group (t)
    int ly   = lane >> 2;         // groupID (g)
    int row0 = blockIdx.y * 128;

    // X loader coords: per thread 2 chunks of (row, 4 k-values = 2 words)
    int xm[2], xw[2];
#pragma unroll
    for (int l = 0; l < 2; l++) {
        int f = tid + l * 256;
        xm[l] = f >> 2;               // row in tile
        xw[l] = (f & 3) * 2;          // word offset within step's 8 words
    }
    // W loader: one uint4 (hi) + uint4 (lo) per thread per step
    int wkp = tid >> 5;               // pair-row 0..7
    int wn0 = (tid & 31) * 4;         // 4 consecutive n-words

    float acc[2][8][4];
#pragma unroll
    for (int i = 0; i < 2; i++)
#pragma unroll
        for (int j = 0; j < 8; j++)
#pragma unroll
            for (int t = 0; t < 4; t++) acc[i][j][t] = 0.f;

    float4 xv[2];                     // fp32 path
    uint2  xh[2], xl[2];              // packed path
    uint4  wh, wl;
    const uint2 z2 = make_uint2(0u, 0u);
    const float4 z4 = make_float4(0.f, 0.f, 0.f, 0.f);

    // ---- prologue: load step 0 ----
#pragma unroll
    for (int l = 0; l < 2; l++) {
        int gr = row0 + xm[l];
        if (PACKED) {
            int gi = gr * 64 + xw[l];
            xh[l] = (gr < N) ? *(const uint2*)&g_xh[gi] : z2;
            xl[l] = (gr < N) ? *(const uint2*)&g_xl[gi] : z2;
        } else {
            xv[l] = (gr < N) ? *(const float4*)(Xf + (size_t)gr * 128 + 2 * xw[l]) : z4;
        }
    }
    wh = *(const uint4*)&g_wph[widx][wkp * 128 + wn0];
    wl = *(const uint4*)&g_wpl[widx][wkp * 128 + wn0];

    // store step 0 into buffer 0
#pragma unroll
    for (int l = 0; l < 2; l++) {
        int base = xm[l] * XPW + xw[l];
        if (PACKED) {
            *(uint2*)&Xph[0][base] = xh[l];
            *(uint2*)&Xpl[0][base] = xl[l];
        } else {
            __nv_bfloat16 h0, l0, h1, l1, h2, l2, h3, l3;
            split_bf16(xv[l].x, h0, l0); split_bf16(xv[l].y, h1, l1);
            split_bf16(xv[l].z, h2, l2); split_bf16(xv[l].w, h3, l3);
            *(uint2*)&Xph[0][base] = make_uint2(pack_bf16(h0, h1), pack_bf16(h2, h3));
            *(uint2*)&Xpl[0][base] = make_uint2(pack_bf16(l0, l1), pack_bf16(l2, l3));
        }
    }
    *(uint4*)&Wph[0][wkp * WPW + wn0] = wh;
    *(uint4*)&Wpl[0][wkp * WPW + wn0] = wl;
    __syncthreads();

    for (int step = 0; step < 8; step++) {
        int cur = step & 1;
        int nxt = cur ^ 1;

        // issue next tile's global loads (latency hidden under MMA)
        if (step < 7) {
            int kkp = (step + 1) * 8;
#pragma unroll
            for (int l = 0; l < 2; l++) {
                int gr = row0 + xm[l];
                if (PACKED) {
                    int gi = gr * 64 + kkp + xw[l];
                    xh[l] = (gr < N) ? *(const uint2*)&g_xh[gi] : z2;
                    xl[l] = (gr < N) ? *(const uint2*)&g_xl[gi] : z2;
                } else {
                    xv[l] = (gr < N)
                        ? *(const float4*)(Xf + (size_t)gr * 128 + 2 * (kkp + xw[l])) : z4;
                }
            }
            wh = *(const uint4*)&g_wph[widx][(kkp + wkp) * 128 + wn0];
            wl = *(const uint4*)&g_wpl[widx][(kkp + wkp) * 128 + wn0];
        }

        // one k16 MMA step from buf[cur]
        uint32_t ah[2][4], al[2][4];
#pragma unroll
        for (int i = 0; i < 2; i++) {
            int r = wm * 32 + i * 16 + ly;
            ah[i][0] = Xph[cur][r * XPW + lx];
            ah[i][1] = Xph[cur][(r + 8) * XPW + lx];
            ah[i][2] = Xph[cur][r * XPW + lx + 4];
            ah[i][3] = Xph[cur][(r + 8) * XPW + lx + 4];
            al[i][0] = Xpl[cur][r * XPW + lx];
            al[i][1] = Xpl[cur][(r + 8) * XPW + lx];
            al[i][2] = Xpl[cur][r * XPW + lx + 4];
            al[i][3] = Xpl[cur][(r + 8) * XPW + lx + 4];
        }
#pragma unroll
        for (int j = 0; j < 8; j++) {
            int n = wn * 64 + j * 8 + ly;
            uint32_t bh0 = Wph[cur][lx * WPW + n];
            uint32_t bh1 = Wph[cur][(lx + 4) * WPW + n];
            uint32_t bl0 = Wpl[cur][lx * WPW + n];
            uint32_t bl1 = Wpl[cur][(lx + 4) * WPW + n];
#pragma unroll
            for (int i = 0; i < 2; i++) {
                mma_bf16(acc[i][j], ah[i], bh0, bh1);   // Ah*Bh
                mma_bf16(acc[i][j], al[i], bh0, bh1);   // Al*Bh
                mma_bf16(acc[i][j], ah[i], bl0, bl1);   // Ah*Bl
            }
        }

        // store next tile into buf[nxt]
        if (step < 7) {
#pragma unroll
            for (int l = 0; l < 2; l++) {
                int base = xm[l] * XPW + xw[l];
                if (PACKED) {
                    *(uint2*)&Xph[nxt][base] = xh[l];
                    *(uint2*)&Xpl[nxt][base] = xl[l];
                } else {
                    __nv_bfloat16 h0, l0, h1, l1, h2, l2, h3, l3;
                    split_bf16(xv[l].x, h0, l0); split_bf16(xv[l].y, h1, l1);
                    split_bf16(xv[l].z, h2, l2); split_bf16(xv[l].w, h3, l3);
                    *(uint2*)&Xph[nxt][base] = make_uint2(pack_bf16(h0, h1), pack_bf16(h2, h3));
                    *(uint2*)&Xpl[nxt][base] = make_uint2(pack_bf16(l0, l1), pack_bf16(l2, l3));
                }
            }
            *(uint4*)&Wph[nxt][wkp * WPW + wn0] = wh;
            *(uint4*)&Wpl[nxt][wkp * WPW + wn0] = wl;
        }
        __syncthreads();
    }

    // epilogue: bias add + guarded store (c0,c1 at row; c2,c3 at row+8)
    bool is_half = (which == 1) || (which == 2);
    float*  Yf = (which == 0) ? g_q : g_s;
    __half* Yh = (which == 1) ? g_kh : g_vh;

#pragma unroll
    for (int i = 0; i < 2; i++) {
        int rg = row0 + wm * 32 + i * 16 + ly;
#pragma unroll
        for (int j = 0; j < 8; j++) {
            int cg = wn * 64 + j * 8 + 2 * lx;
            float2 bb = *(const float2*)(bias + cg);
            float o00 = acc[i][j][0] + bb.x, o01 = acc[i][j][1] + bb.y;
            float o10 = acc[i][j][2] + bb.x, o11 = acc[i][j][3] + bb.y;
            if (is_half) {
                if (rg < N)
                    *(__half2*)(Yh + (size_t)rg * 128 + cg) = __floats2half2_rn(o00, o01);
                if (rg + 8 < N)
                    *(__half2*)(Yh + (size_t)(rg + 8) * 128 + cg) = __floats2half2_rn(o10, o11);
            } else {
                if (rg < N)
                    *(float2*)(Yf + (size_t)rg * 128 + cg) = make_float2(o00, o01);
                if (rg + 8 < N)
                    *(float2*)(Yf + (size_t)(rg + 8) * 128 + cg) = make_float2(o10, o11);
            }
        }
    }
}

// ---------------- fused attention: gather + online softmax + skip ----------
// TWO nodes per warp: each 16-lane half handles one node, 8 channels per lane.
// Layer 0 (outp==null): epilogue writes packed bf16 hi/lo X for layer-1 GEMM.
__device__ __forceinline__ float dot8(float4 q0, float4 q1, uint4 u)
{
    float2 f0 = __half22float2(*reinterpret_cast<__half2*>(&u.x));
    float2 f1 = __half22float2(*reinterpret_cast<__half2*>(&u.y));
    float2 f2 = __half22float2(*reinterpret_cast<__half2*>(&u.z));
    float2 f3 = __half22float2(*reinterpret_cast<__half2*>(&u.w));
    return q0.x * f0.x + q0.y * f0.y + q0.z * f1.x + q0.w * f1.y
         + q1.x * f2.x + q1.y * f2.y + q1.z * f3.x + q1.w * f3.y;
}

__device__ __forceinline__ void acc8(float4& a0, float4& a1, float w, uint4 u)
{
    float2 f0 = __half22float2(*reinterpret_cast<__half2*>(&u.x));
    float2 f1 = __half22float2(*reinterpret_cast<__half2*>(&u.y));
    float2 f2 = __half22float2(*reinterpret_cast<__half2*>(&u.z));
    float2 f3 = __half22float2(*reinterpret_cast<__half2*>(&u.w));
    a0.x += w * f0.x; a0.y += w * f0.y; a0.z += w * f1.x; a0.w += w * f1.y;
    a1.x += w * f2.x; a1.y += w * f2.y; a1.z += w * f3.x; a1.w += w * f3.y;
}

__global__ void attn_gather_kernel(float* __restrict__ outp, int N, int do_relu)
{
    int warp_id = blockIdx.x * 8 + (threadIdx.x >> 5);
    int lane = threadIdx.x & 31;
    int half = lane >> 4;                 // 0 or 1: which node in this warp
    int hl   = lane & 15;                 // lane within half; channels [8hl, 8hl+8)
    int node = warp_id * 2 + half;
    if (node >= N) return;
    unsigned mask = 0xFFFFu << (half * 16);

    size_t off = (size_t)node * D;
    float4 q0 = *((const float4*)(g_q + off) + 2 * hl);
    float4 q1 = *((const float4*)(g_q + off) + 2 * hl + 1);

    int beg = g_rowptr[node];
    int end = g_rowptr[node + 1];

    float m = NEG_INF;
    float den = 0.f;
    float4 acc0 = make_float4(0.f, 0.f, 0.f, 0.f);
    float4 acc1 = make_float4(0.f, 0.f, 0.f, 0.f);

    int i = beg;
    for (; i + 4 <= end; i += 4) {
        int s0 = __ldg(&g_csrc[i]);
        int s1 = __ldg(&g_csrc[i + 1]);
        int s2 = __ldg(&g_csrc[i + 2]);
        int s3 = __ldg(&g_csrc[i + 3]);
        uint4 k0 = __ldg((const uint4*)(g_kh + (size_t)s0 * D) + hl);
        uint4 k1 = __ldg((const uint4*)(g_kh + (size_t)s1 * D) + hl);
        uint4 k2 = __ldg((const uint4*)(g_kh + (size_t)s2 * D) + hl);
        uint4 k3 = __ldg((const uint4*)(g_kh + (size_t)s3 * D) + hl);
        uint4 v0 = __ldg((const uint4*)(g_vh + (size_t)s0 * D) + hl);
        uint4 v1 = __ldg((const uint4*)(g_vh + (size_t)s1 * D) + hl);
        uint4 v2 = __ldg((const uint4*)(g_vh + (size_t)s2 * D) + hl);
        uint4 v3 = __ldg((const uint4*)(g_vh + (size_t)s3 * D) + hl);

        float a0 = dot8(q0, q1, k0);
        float a1 = dot8(q0, q1, k1);
        float a2 = dot8(q0, q1, k2);
        float a3 = dot8(q0, q1, k3);
        a0 = (a0 + __shfl_xor_sync(mask, a0, 1)) * ATT_SCALE;
        a1 = (a1 + __shfl_xor_sync(mask, a1, 1)) * ATT_SCALE;
        a2 = (a2 + __shfl_xor_sync(mask, a2, 1)) * ATT_SCALE;
        a3 = (a3 + __shfl_xor_sync(mask, a3, 1)) * ATT_SCALE;

        float mx = fmaxf(fmaxf(a0, a1), fmaxf(a2, a3));
        float newm = fmaxf(m, mx);
        float c  = __expf(m - newm);      // first group: exp(-inf)=0
        float w0 = __expf(a0 - newm);
        float w1 = __expf(a1 - newm);
        float w2 = __expf(a2 - newm);
        float w3 = __expf(a3 - newm);
        den = den * c + (w0 + w1) + (w2 + w3);
        acc0.x *= c; acc0.y *= c; acc0.z *= c; acc0.w *= c;
        acc1.x *= c; acc1.y *= c; acc1.z *= c; acc1.w *= c;
        acc8(acc0, acc1, w0, v0);
        acc8(acc0, acc1, w1, v1);
        acc8(acc0, acc1, w2, v2);
        acc8(acc0, acc1, w3, v3);
        m = newm;
    }
    for (; i < end; i++) {
        int s = __ldg(&g_csrc[i]);
        uint4 kv = __ldg((const uint4*)(g_kh + (size_t)s * D) + hl);
        uint4 vv = __ldg((const uint4*)(g_vh + (size_t)s * D) + hl);
        float a = dot8(q0, q1, kv);
        a = (a + __shfl_xor_sync(mask, a, 1)) * ATT_SCALE;
        float newm = fmaxf(m, a);
        float c = __expf(m - newm);
        float w = __expf(a - newm);
        den = den * c + w;
        acc0.x *= c; acc0.y *= c; acc0.z *= c; acc0.w *= c;
        acc1.x *= c; acc1.y *= c; acc1.z *= c; acc1.w *= c;
        acc8(acc0, acc1, w, vv);
        m = newm;
    }

    float4 sv0 = *((const float4*)(g_s + off) + 2 * hl);
    float4 sv1 = *((const float4*)(g_s + off) + 2 * hl + 1);
    float inv = (den > 0.f) ? 1.f / den : 0.f;
    float o[8];
    o[0] = sv0.x + acc0.x * inv; o[1] = sv0.y + acc0.y * inv;
    o[2] = sv0.z + acc0.z * inv; o[3] = sv0.w + acc0.w * inv;
    o[4] = sv1.x + acc1.x * inv; o[5] = sv1.y + acc1.y * inv;
    o[6] = sv1.z + acc1.z * inv; o[7] = sv1.w + acc1.w * inv;
    if (do_relu) {
#pragma unroll
        for (int t = 0; t < 8; t++) o[t] = fmaxf(o[t], 0.f);
    }

    if (outp) {
        *((float4*)(outp + off) + 2 * hl)     = make_float4(o[0], o[1], o[2], o[3]);
        *((float4*)(outp + off) + 2 * hl + 1) = make_float4(o[4], o[5], o[6], o[7]);
    } else {
        // pack for layer-1 GEMM: 4 hi words + 4 lo words per lane
        __nv_bfloat16 hb[8], lb[8];
#pragma unroll
        for (int t = 0; t < 8; t++) split_bf16(o[t], hb[t], lb[t]);
        int wi = node * 64 + 4 * hl;
        *(uint4*)&g_xh[wi] = make_uint4(pack_bf16(hb[0], hb[1]), pack_bf16(hb[2], hb[3]),
                                        pack_bf16(hb[4], hb[5]), pack_bf16(hb[6], hb[7]));
        *(uint4*)&g_xl[wi] = make_uint4(pack_bf16(lb[0], lb[1]), pack_bf16(lb[2], lb[3]),
                                        pack_bf16(lb[4], lb[5]), pack_bf16(lb[6], lb[7]));
    }
}

// ---------------- host ------------------------------------------------------
extern "C" void kernel_launch(void* const* d_in, const int* in_sizes, int n_in,
                              void* d_out, int out_size)
{
    const float* x = (const float*)d_in[0];
    const int* ei32 = (const int*)d_in[1];
    int N = in_sizes[0] / 128;
    int E = in_sizes[1] / 2;

    const float* W[2][4] = {
        {(const float*)d_in[3], (const float*)d_in[5], (const float*)d_in[7], (const float*)d_in[9]},
        {(const float*)d_in[11], (const float*)d_in[13], (const float*)d_in[15], (const float*)d_in[17]}
    };
    const float* B[2][4] = {
        {(const float*)d_in[4], (const float*)d_in[6], (const float*)d_in[8], (const float*)d_in[10]},
        {(const float*)d_in[12], (const float*)d_in[14], (const float*)d_in[16], (const float*)d_in[18]}
    };

    // one-time side stream + fork/join events (resources only; work is
    // identical on every call)
    static cudaStream_t s2 = nullptr;
    static cudaEvent_t evFork = nullptr, evW = nullptr, evJoin = nullptr;
    if (!s2) {
        cudaStreamCreateWithFlags(&s2, cudaStreamNonBlocking);
        cudaEventCreateWithFlags(&evFork, cudaEventDisableTiming);
        cudaEventCreateWithFlags(&evW, cudaEventDisableTiming);
        cudaEventCreateWithFlags(&evJoin, cudaEventDisableTiming);
    }

    int Ntot = N + 1;
    int nscan = (Ntot + 1023) / 1024;

    // fork: weight prep + CSR build on s2
    cudaEventRecord(evFork, 0);
    cudaStreamWaitEvent(s2, evFork, 0);
    w_prep_kernel<<<256, 256, 0, s2>>>(W[0][0], W[0][1], W[0][2], W[0][3],
                                       W[1][0], W[1][1], W[1][2], W[1][3]);
    cudaEventRecord(evW, s2);
    detect_kernel<<<1, 256, 0, s2>>>(ei32);
    zero_cnt_kernel<<<(Ntot + 255) / 256, 256, 0, s2>>>(N);
    convert_hist_kernel<<<(E + 255) / 256, 256, 0, s2>>>(ei32, E);
    scan1_kernel<<<nscan, 1024, 0, s2>>>(Ntot);
    scan2_kernel<<<1, 32, 0, s2>>>(nscan);
    scan3_kernel<<<nscan, 1024, 0, s2>>>(Ntot);
    scatter_kernel<<<(E + 255) / 256, 256, 0, s2>>>(E);
    cudaEventRecord(evJoin, s2);

    dim3 ggrid(4, (N + 127) / 128);
    int attn_blocks = (N + 15) / 16;   // 2 nodes per warp, 8 warps per block

    // layer 0 (fp32 X, in-kernel split; waits only for packed weights)
    cudaStreamWaitEvent(0, evW, 0);
    gemm4_kernel<false><<<ggrid, 256>>>(x, 0, B[0][0], B[0][1], B[0][2], B[0][3], N);
    cudaStreamWaitEvent(0, evJoin, 0);   // join: attention needs CSR
    attn_gather_kernel<<<attn_blocks, 256>>>(nullptr, N, 1);  // writes packed X

    // layer 1 (packed X path)
    gemm4_kernel<true><<<ggrid, 256>>>(nullptr, 1, B[1][0], B[1][1], B[1][2], B[1][3], N);
    attn_gather_kernel<<<attn_blocks, 256>>>((float*)d_out, N, 0);
}